// round 17
// baseline (speedup 1.0000x reference)
#include <cuda_runtime.h>
#include <cuda_bf16.h>

#define L_SEQ 1024
#define NPOS  64
#define ROWS_TOTAL (4 * 12 * 1024)

// Scratch: lint[row][n] = q[row,:] . pe[:,n]
__device__ float g_lint[(size_t)ROWS_TOTAL * NPOS];

__device__ __forceinline__ void fma2(unsigned long long& acc,
                                     unsigned long long a,
                                     unsigned long long b) {
    asm("fma.rn.f32x2 %0, %1, %2, %0;" : "+l"(acc) : "l"(a), "l"(b));
}

// ---------------------------------------------------------------------------
// Kernel 1: lint = query @ pos_emb   ([49152,64] @ [64,64])
// Block = 256 threads (8 warps), 64 rows. Warp layout:
//   rowgrp = w>>2 (rows rowgrp*32 + lane), colgrp = w&3 (cols colgrp*16).
// pe staged in smem, read WARP-UNIFORM (broadcast LDS.128, 4 per k per warp);
// q staged pitched (68 floats) -> one conflict-free LDS.128 per 4 k.
// Packed f32x2 FMA. LDS instr count ~halved vs prior gemv.
// ---------------------------------------------------------------------------
__global__ __launch_bounds__(256) void gemv4(
    const float* __restrict__ q, const float* __restrict__ pe)
{
    __shared__ float pesh[64 * 64];     // [k][n], 16KB
    __shared__ float qsh[64 * 68];      // [row][k], pitch 68 (17 float4)

    const int t    = threadIdx.x;
    const int lane = t & 31;
    const int w    = t >> 5;

    // Stage pe (coalesced).
    {
        const float4* src = reinterpret_cast<const float4*>(pe);
        float4*       dst = reinterpret_cast<float4*>(pesh);
        #pragma unroll
        for (int i = 0; i < 4; i++) dst[t + 256 * i] = __ldg(&src[t + 256 * i]);
    }
    // Stage q (coalesced read, pitched write; near conflict-free STS.128).
    const int base = blockIdx.x * 64;
    {
        const float4* qsrc = reinterpret_cast<const float4*>(q + (size_t)base * 64);
        #pragma unroll
        for (int h = 0; h < 4; h++) {
            const int i = t + 256 * h;        // float4 index
            const float4 v = __ldg(&qsrc[i]);
            const int row = i >> 4;           // 16 float4 per row
            const int c4  = i & 15;
            *reinterpret_cast<float4*>(&qsh[row * 68 + c4 * 4]) = v;
        }
    }
    __syncthreads();

    const int row = ((w >> 2) << 5) + lane;   // 0..63
    const int cb  = (w & 3) * 16;             // col base

    unsigned long long acc[8];
    #pragma unroll
    for (int i = 0; i < 8; i++) acc[i] = 0ull;

    const float* qrow = &qsh[row * 68];
    #pragma unroll
    for (int kk = 0; kk < 16; kk++) {
        const float4 qv = *reinterpret_cast<const float4*>(&qrow[kk * 4]); // LDS.128, conflict-free
        const float qk4[4] = {qv.x, qv.y, qv.z, qv.w};
        #pragma unroll
        for (int j = 0; j < 4; j++) {
            const int k = kk * 4 + j;
            unsigned long long q2;
            asm("mov.b64 %0, {%1, %1};" : "=l"(q2) : "r"(__float_as_uint(qk4[j])));
            const ulonglong2* pp = reinterpret_cast<const ulonglong2*>(&pesh[k * NPOS + cb]);
            const ulonglong2 pv0 = pp[0];   // cols cb..cb+3   (uniform -> broadcast)
            const ulonglong2 pv1 = pp[1];   // cols cb+4..cb+7
            fma2(acc[0], pv0.x, q2);
            fma2(acc[1], pv0.y, q2);
            fma2(acc[2], pv1.x, q2);
            fma2(acc[3], pv1.y, q2);
            const ulonglong2 pv2 = pp[2];   // cols cb+8..cb+11
            const ulonglong2 pv3 = pp[3];   // cols cb+12..cb+15
            fma2(acc[4], pv2.x, q2);
            fma2(acc[5], pv2.y, q2);
            fma2(acc[6], pv3.x, q2);
            fma2(acc[7], pv3.y, q2);
        }
    }

    // Store 16 cols for this (row, colgrp). Default caching: cope_main re-reads via L2.
    ulonglong2* dst = reinterpret_cast<ulonglong2*>(&g_lint[(size_t)(base + row) * NPOS + cb]);
    ulonglong2 r0; r0.x = acc[0]; r0.y = acc[1];
    ulonglong2 r1; r1.x = acc[2]; r1.y = acc[3];
    ulonglong2 r2; r2.x = acc[4]; r2.y = acc[5];
    ulonglong2 r3; r3.x = acc[6]; r3.y = acc[7];
    dst[0] = r0; dst[1] = r1; dst[2] = r2; dst[3] = r3;
}

// ---------------------------------------------------------------------------
// Kernel 2 (UNCHANGED from R7 — proven 59.8us): per row of 1024:
// gates = sigmoid(attn) (diag zeroed), pos = clamp(suffix_sum, 0, 63),
// out = lerp(Lg[floor], Lg[floor+1], frac). 128 threads; thread t owns
// elements [4t,4t+4) and [512+4t,512+4t+4).
// ---------------------------------------------------------------------------
__global__ __launch_bounds__(128) void cope_main(
    const float* __restrict__ attn,
    float* __restrict__ out)
{
    const int row  = blockIdx.x;
    const int diag = row & (L_SEQ - 1);
    const int t    = threadIdx.x;
    const int lane = t & 31;
    const int w    = t >> 5;

    __shared__ float Lg[NPOS + 1];        // Lg[64] = Lg[63] (weight 0 there)
    __shared__ float wsumA[4], wsumB[4];

    const float4* arow = reinterpret_cast<const float4*>(attn) + (size_t)row * (L_SEQ / 4);
    const float4 va = __ldcs(&arow[t]);
    const float4 vb = __ldcs(&arow[t + 128]);
    if (t < NPOS + 1) {
        const int idx = (t < NPOS) ? t : (NPOS - 1);
        Lg[t] = g_lint[(size_t)row * NPOS + idx];
    }

    float g[8];
    g[0] = __fdividef(1.0f, 1.0f + __expf(-va.x));
    g[1] = __fdividef(1.0f, 1.0f + __expf(-va.y));
    g[2] = __fdividef(1.0f, 1.0f + __expf(-va.z));
    g[3] = __fdividef(1.0f, 1.0f + __expf(-va.w));
    g[4] = __fdividef(1.0f, 1.0f + __expf(-vb.x));
    g[5] = __fdividef(1.0f, 1.0f + __expf(-vb.y));
    g[6] = __fdividef(1.0f, 1.0f + __expf(-vb.z));
    g[7] = __fdividef(1.0f, 1.0f + __expf(-vb.w));

    const int cA = t << 2;
    const int cB = 512 + (t << 2);
    #pragma unroll
    for (int i = 0; i < 4; i++) if (cA + i == diag) g[i] = 0.0f;
    #pragma unroll
    for (int i = 0; i < 4; i++) if (cB + i == diag) g[4 + i] = 0.0f;

    const float sA = g[0] + g[1] + g[2] + g[3];
    const float sB = g[4] + g[5] + g[6] + g[7];

    float iA = sA, iB = sB;
    #pragma unroll
    for (int off = 1; off < 32; off <<= 1) {
        const float nA = __shfl_up_sync(0xffffffffu, iA, off);
        const float nB = __shfl_up_sync(0xffffffffu, iB, off);
        if (lane >= off) { iA += nA; iB += nB; }
    }
    if (lane == 31) { wsumA[w] = iA; wsumB[w] = iB; }
    __syncthreads();

    float totA = 0.0f, totB = 0.0f, preA = 0.0f, preB = 0.0f;
    #pragma unroll
    for (int k = 0; k < 4; k++) {
        const float a = wsumA[k], b = wsumB[k];
        totA += a; totB += b;
        if (k < w) { preA += a; preB += b; }
    }
    const float total = totA + totB;
    const float exclA = preA + iA - sA;
    const float exclB = totA + preB + iB - sB;

    const float Lg63 = Lg[NPOS - 1];
    float4 oA, oB;

    {
        const float p0 = total - exclA;
        const float p1 = p0 - g[0];
        const float p2 = p1 - g[1];
        const float p3 = p2 - g[2];
        if (p3 >= 63.0f) {
            oA.x = Lg63; oA.y = Lg63; oA.z = Lg63; oA.w = Lg63;
        } else {
            float p, pf, ww; int fi;
            p = fminf(fmaxf(p0, 0.0f), 63.0f); pf = floorf(p); ww = p - pf; fi = (int)pf;
            oA.x = Lg[fi] + ww * (Lg[fi + 1] - Lg[fi]);
            p = fminf(fmaxf(p1, 0.0f), 63.0f); pf = floorf(p); ww = p - pf; fi = (int)pf;
            oA.y = Lg[fi] + ww * (Lg[fi + 1] - Lg[fi]);
            p = fminf(fmaxf(p2, 0.0f), 63.0f); pf = floorf(p); ww = p - pf; fi = (int)pf;
            oA.z = Lg[fi] + ww * (Lg[fi + 1] - Lg[fi]);
            p = fminf(fmaxf(p3, 0.0f), 63.0f); pf = floorf(p); ww = p - pf; fi = (int)pf;
            oA.w = Lg[fi] + ww * (Lg[fi + 1] - Lg[fi]);
        }
    }
    {
        const float p0 = total - exclB;
        const float p1 = p0 - g[4];
        const float p2 = p1 - g[5];
        const float p3 = p2 - g[6];
        if (p3 >= 63.0f) {
            oB.x = Lg63; oB.y = Lg63; oB.z = Lg63; oB.w = Lg63;
        } else {
            float p, pf, ww; int fi;
            p = fminf(fmaxf(p0, 0.0f), 63.0f); pf = floorf(p); ww = p - pf; fi = (int)pf;
            oB.x = Lg[fi] + ww * (Lg[fi + 1] - Lg[fi]);
            p = fminf(fmaxf(p1, 0.0f), 63.0f); pf = floorf(p); ww = p - pf; fi = (int)pf;
            oB.y = Lg[fi] + ww * (Lg[fi + 1] - Lg[fi]);
            p = fminf(fmaxf(p2, 0.0f), 63.0f); pf = floorf(p); ww = p - pf; fi = (int)pf;
            oB.z = Lg[fi] + ww * (Lg[fi + 1] - Lg[fi]);
            p = fminf(fmaxf(p3, 0.0f), 63.0f); pf = floorf(p); ww = p - pf; fi = (int)pf;
            oB.w = Lg[fi] + ww * (Lg[fi + 1] - Lg[fi]);
        }
    }

    float4* orow = reinterpret_cast<float4*>(out) + (size_t)row * (L_SEQ / 4);
    __stcs(&orow[t],       oA);
    __stcs(&orow[t + 128], oB);
}

extern "C" void kernel_launch(void* const* d_in, const int* in_sizes, int n_in,
                              void* d_out, int out_size) {
    const float* query = (const float*)d_in[0];   // [4,12,1024,64]
    const float* attn  = (const float*)d_in[1];   // [4,12,1024,1024]
    const float* pe    = (const float*)d_in[2];   // [64,64]
    float* out = (float*)d_out;                   // [4,12,1024,1024]

    const int rows = in_sizes[1] / L_SEQ;         // 49152
    gemv4<<<rows / 64, 256>>>(query, pe);
    cope_main<<<rows, 128>>>(attn, out);
}